// round 17
// baseline (speedup 1.0000x reference)
#include <cuda_runtime.h>
#include <cuda_fp16.h>
#include <cstdint>

// ---------------- scratch (no cudaMalloc allowed) ----------------
__device__ __half g_h1h[256 * 1024 * 8];   // LSTM1 outputs as fp16, [B][S][8], 4MB

// ---------------- fast activations: MUFU.TANH based ----------------
__device__ __forceinline__ float tanhapx(float x) {
    float r; asm("tanh.approx.f32 %0, %1;" : "=f"(r) : "f"(x)); return r;
}
__device__ __forceinline__ __half2 u2h(unsigned u) {
    return *reinterpret_cast<__half2*>(&u);
}
__device__ __forceinline__ unsigned h2u(__half2 h) {
    return *reinterpret_cast<unsigned*>(&h);
}

__device__ __forceinline__ void lstm_upd(float& c, float& h,
                                         float gi, float gf, float gg, float go) {
    float ti = tanhapx(0.5f * gi);
    float tf = tanhapx(0.5f * gf);
    float tg = tanhapx(gg);
    float to = tanhapx(0.5f * go);
    float p  = fmaf(0.5f * ti, tg, 0.5f * tg);          // sig(i)*tanh(g)
    c = fmaf(0.5f * tf, c, fmaf(0.5f, c, p));           // sig(f)*c + p
    float tc = tanhapx(c);
    h = fmaf(0.5f * to, tc, 0.5f * tc);                 // sig(o)*tanh(c)
}

// =================================================================
// Kernel 1: LSTM1, half2 arithmetic (R16-measured ~62 us). Unchanged.
// =================================================================
__global__ __launch_bounds__(256) void lstm1_kernel(
    const float* __restrict__ x,
    const float* __restrict__ W_ih1, const float* __restrict__ W_hh1,
    const float* __restrict__ b_ih1, const float* __restrict__ b_hh1)
{
    __shared__ __half2 sT[8][16];     // sT[e][m] = (W_hh1[2m][e], W_hh1[2m+1][e])
    __shared__ __half2 sI[16];        // W_ih pairs
    __shared__ __half2 sB[16];        // fused bias pairs
    int tid = threadIdx.x;
    if (tid < 32) {
        ((__half*)sI)[tid] = __float2half_rn(W_ih1[tid]);
        ((__half*)sB)[tid] = __float2half_rn(b_ih1[tid] + b_hh1[tid]);
    }
    {
        int g = tid >> 3, e = tid & 7;
        ((__half*)&sT[e][0])[g] = __float2half_rn(W_hh1[g * 8 + e]);
    }
    __syncthreads();

    __half2 rI[16], rB[16];
#pragma unroll
    for (int m = 0; m < 16; m++) { rI[m] = sI[m]; rB[m] = sB[m]; }

    long n = (long)blockIdx.x * 256 + tid;
    const float4* xp = (const float4*)(x + n * 16);
    float4 xq[4];
    xq[0] = xp[0]; xq[1] = xp[1]; xq[2] = xp[2]; xq[3] = xp[3];
    float xv[16];
#pragma unroll
    for (int i = 0; i < 4; i++) {
        xv[4 * i + 0] = xq[i].x; xv[4 * i + 1] = xq[i].y;
        xv[4 * i + 2] = xq[i].z; xv[4 * i + 3] = xq[i].w;
    }

    float h[8], c[8];
#pragma unroll
    for (int d = 0; d < 8; d++) { h[d] = 0.f; c[d] = 0.f; }

#pragma unroll
    for (int t = 0; t < 16; t++) {
        __half2 xt2 = __float2half2_rn(xv[t]);
        __half2 acc[16];
#pragma unroll
        for (int m = 0; m < 16; m++)
            acc[m] = __hfma2(rI[m], xt2, rB[m]);
#pragma unroll
        for (int e = 0; e < 8; e++) {
            __half2 he2 = __float2half2_rn(h[e]);
            const __half2* T = sT[e];
#pragma unroll
            for (int m = 0; m < 16; m++)
                acc[m] = __hfma2(T[m], he2, acc[m]);
        }
#pragma unroll
        for (int q = 0; q < 4; q++) {
            float2 fi = __half22float2(acc[q]);
            float2 ff = __half22float2(acc[4 + q]);
            float2 fg = __half22float2(acc[8 + q]);
            float2 fo = __half22float2(acc[12 + q]);
            lstm_upd(c[2 * q + 0], h[2 * q + 0], fi.x, ff.x, fg.x, fo.x);
            lstm_upd(c[2 * q + 1], h[2 * q + 1], fi.y, ff.y, fg.y, fo.y);
        }
    }

    __half2 p0 = __floats2half2_rn(h[0], h[1]);
    __half2 p1 = __floats2half2_rn(h[2], h[3]);
    __half2 p2 = __floats2half2_rn(h[4], h[5]);
    __half2 p3 = __floats2half2_rn(h[6], h[7]);
    uint4 u;
    u.x = *reinterpret_cast<uint32_t*>(&p0);
    u.y = *reinterpret_cast<uint32_t*>(&p1);
    u.z = *reinterpret_cast<uint32_t*>(&p2);
    u.w = *reinterpret_cast<uint32_t*>(&p3);
    *reinterpret_cast<uint4*>(g_h1h + n * 8) = u;
}

// =================================================================
// Kernel 2: LSTM2, occupancy-2 redesign.
// 256 CTAs x 512 threads, ONE batch per CTA, 2 CTAs resident per SM
// (their phase A / phase B interleave -> fma pipe stays fed).
// Thread j owns gate-row j for this CTA's batch:
//   k [0,64)   (q 0..7):  32 half2 in REGISTERS (ih 0..7 + hh 0..55)
//   k [64,136) (q 8..16): 36 half2 in SMEM, slot stride 144 B
//                         (9 uint4/row; R4-validated conflict-free)
// Chain structure identical to R10: 2 chains x 8-deep HFMA2 per 32-k
// block, fp32 flush -> same numerics as the 941us kernel, per batch.
// =================================================================
__global__ void __launch_bounds__(512, 2) lstm2_kernel(
    const float* __restrict__ W_ih2, const float* __restrict__ W_hh2,
    const float* __restrict__ b_ih2, const float* __restrict__ b_hh2,
    const float* __restrict__ W1, const float* __restrict__ b1,
    const float* __restrict__ W2, const float* __restrict__ b2,
    float* __restrict__ out)
{
    extern __shared__ char smW[];          // 512 * 144 B weight slots
    __shared__ __half2 vecH[80];           // 68 used (x|h), pad to 80
    __shared__ float   gst[512];
    __shared__ float   hb[128];
    __shared__ float   red[2];

    const int t = threadIdx.x;
    const int j = t;                       // gate row
    const int b = blockIdx.x;              // batch

    // ---- smem weights: hh cols 56..127 (9 uint4 per row) ----
    for (int idx = t; idx < 512 * 9; idx += 512) {
        int row = idx / 9, g = idx - row * 9;
        const float4* src = (const float4*)(W_hh2 + row * 128 + 56 + g * 8);
        float4 v0 = src[0], v1 = src[1];
        uint4 u;
        u.x = h2u(__floats2half2_rn(v0.x, v0.y));
        u.y = h2u(__floats2half2_rn(v0.z, v0.w));
        u.z = h2u(__floats2half2_rn(v1.x, v1.y));
        u.w = h2u(__floats2half2_rn(v1.z, v1.w));
        *reinterpret_cast<uint4*>(smW + row * 144 + g * 16) = u;
    }

    // ---- register weights: k 0..63 (ih 8 + hh 0..55) ----
    __half2 wreg[32];
    {
        const float4* wi4 = (const float4*)(W_ih2 + j * 8);
#pragma unroll
        for (int q = 0; q < 2; q++) {
            float4 v = wi4[q];
            wreg[2 * q + 0] = __floats2half2_rn(v.x, v.y);
            wreg[2 * q + 1] = __floats2half2_rn(v.z, v.w);
        }
        const float4* wh4 = (const float4*)(W_hh2 + j * 128);
#pragma unroll
        for (int q = 0; q < 14; q++) {
            float4 v = wh4[q];
            wreg[4 + 2 * q + 0] = __floats2half2_rn(v.x, v.y);
            wreg[4 + 2 * q + 1] = __floats2half2_rn(v.z, v.w);
        }
    }
    const float bias = b_ih2[j] + b_hh2[j];

    // ---- init vec, stage x_0, prefetch x_1 ----
    if (t < 40) ((float*)vecH)[t] = 0.f;
    __syncthreads();
    if (t < 8)
        ((__half*)vecH)[t] = g_h1h[((long)b * 1024 + 0) * 8 + t];
    float c_ = 0.f, h_ = 0.f;              // state for threads t<128 (d=t)
    __half xr = __float2half_rn(0.f);      // x prefetch (threads 128..135)
    if (t >= 128 && t < 136)
        xr = g_h1h[((long)b * 1024 + 1) * 8 + (t - 128)];
    __syncthreads();

    const uint4* V  = (const uint4*)vecH;                  // V[q] = 8 k's
    const uint4* Wq = (const uint4*)(smW + j * 144);       // q 8..16
    const __half2 hz = __float2half2_rn(0.f);

    for (int step = 0; step < 1024; step++) {
        float a0 = bias;
        // ---- blk 0/1: q 0..7 from registers ----
#pragma unroll
        for (int blk = 0; blk < 2; blk++) {
            __half2 sA = hz, sB = hz;
#pragma unroll
            for (int qq = 0; qq < 4; qq++) {
                int q = blk * 4 + qq;
                uint4 u = V[q];
                sA = __hfma2(wreg[4 * q + 0], u2h(u.x), sA);
                sB = __hfma2(wreg[4 * q + 1], u2h(u.y), sB);
                sA = __hfma2(wreg[4 * q + 2], u2h(u.z), sA);
                sB = __hfma2(wreg[4 * q + 3], u2h(u.w), sB);
            }
            float2 f = __half22float2(__hadd2(sA, sB));
            a0 += f.x; a0 += f.y;
        }
        // ---- blk 2/3: q 8..15 from smem ----
#pragma unroll
        for (int blk = 0; blk < 2; blk++) {
            __half2 sA = hz, sB = hz;
#pragma unroll
            for (int qq = 0; qq < 4; qq++) {
                int q = 8 + blk * 4 + qq;
                uint4 u = V[q];
                uint4 w = Wq[q - 8];
                sA = __hfma2(u2h(w.x), u2h(u.x), sA);
                sB = __hfma2(u2h(w.y), u2h(u.y), sB);
                sA = __hfma2(u2h(w.z), u2h(u.z), sA);
                sB = __hfma2(u2h(w.w), u2h(u.w), sB);
            }
            float2 f = __half22float2(__hadd2(sA, sB));
            a0 += f.x; a0 += f.y;
        }
        // ---- tail: q 16 ----
        {
            uint4 u = V[16];
            uint4 w = Wq[8];
            __half2 sA = __hfma2(u2h(w.x), u2h(u.x), hz);
            __half2 sB = __hfma2(u2h(w.y), u2h(u.y), hz);
            sA = __hfma2(u2h(w.z), u2h(u.z), sA);
            sB = __hfma2(u2h(w.w), u2h(u.w), sB);
            float2 f = __half22float2(__hadd2(sA, sB));
            a0 += f.x; a0 += f.y;
        }
        gst[j] = a0;
        __syncthreads();

        // ---- phase B: activations (threads 0..127) + x staging ----
        if (t < 128) {
            float gi = gst[t];
            float gf = gst[128 + t];
            float gg = gst[256 + t];
            float go = gst[384 + t];
            float ti = tanhapx(0.5f * gi);
            float tf = tanhapx(0.5f * gf);
            float tg = tanhapx(gg);
            float to = tanhapx(0.5f * go);
            float pq = fmaf(0.5f * ti, tg, 0.5f * tg);
            c_ = fmaf(0.5f * tf, c_, fmaf(0.5f, c_, pq));
            float tc = tanhapx(c_);
            h_ = fmaf(0.5f * to, tc, 0.5f * tc);
            ((__half*)vecH)[8 + t] = __float2half_rn(h_);
        } else if (t < 136) {
            int k = t - 128;
            ((__half*)vecH)[k] = xr;                  // x_{step+1}
            if (step + 2 < 1024)
                xr = g_h1h[((long)b * 1024 + step + 2) * 8 + k];
        }
        __syncthreads();
    }

    // ---- epilogue: out[b] = (h @ W1^T + b1) @ W2^T + b2 ----
    if (t < 128) hb[t] = h_;
    __syncthreads();
    if (t < 64) {
        const float* w1r = W1 + t * 128;
        float m_ = b1[t];
#pragma unroll
        for (int k = 0; k < 128; k++) m_ = fmaf(w1r[k], hb[k], m_);
        float pr = m_ * W2[t];
#pragma unroll
        for (int off = 16; off; off >>= 1)
            pr += __shfl_xor_sync(0xffffffff, pr, off);
        if ((t & 31) == 0) red[t >> 5] = pr;
    }
    __syncthreads();
    if (t == 0)
        out[b] = red[0] + red[1] + b2[0];
}

#define SMW_BYTES (512 * 144)

// =================================================================
extern "C" void kernel_launch(void* const* d_in, const int* in_sizes, int n_in,
                              void* d_out, int out_size) {
    const float* x     = (const float*)d_in[0];
    // d_in[1] = data (unused)
    const float* W_ih1 = (const float*)d_in[2];
    const float* W_hh1 = (const float*)d_in[3];
    const float* b_ih1 = (const float*)d_in[4];
    const float* b_hh1 = (const float*)d_in[5];
    const float* W_ih2 = (const float*)d_in[6];
    const float* W_hh2 = (const float*)d_in[7];
    const float* b_ih2 = (const float*)d_in[8];
    const float* b_hh2 = (const float*)d_in[9];
    const float* W1    = (const float*)d_in[10];
    const float* b1    = (const float*)d_in[11];
    const float* W2    = (const float*)d_in[12];
    const float* b2    = (const float*)d_in[13];
    float* out = (float*)d_out;

    lstm1_kernel<<<1024, 256>>>(x, W_ih1, W_hh1, b_ih1, b_hh1);

    cudaFuncSetAttribute(lstm2_kernel,
                         cudaFuncAttributeMaxDynamicSharedMemorySize, SMW_BYTES);
    lstm2_kernel<<<256, 512, SMW_BYTES>>>(W_ih2, W_hh2, b_ih2, b_hh2,
                                          W1, b1, W2, b2, out);
}